// round 1
// baseline (speedup 1.0000x reference)
#include <cuda_runtime.h>
#include <cstdint>

// ---------------- Problem constants (fixed by the dataset) ----------------
#define D_MODEL   256
#define N_HEADS   8
#define HEAD_DIM  32
#define N_LEVELS  4
#define N_POINTS  4
#define LEN_IN    22223
#define NBATCH    2
#define TOTQ      (NBATCH * LEN_IN)   // 44446

__device__ __constant__ int   c_W[4] = {167, 84, 42, 21};
__device__ __constant__ int   c_H[4] = {100, 50, 25, 13};
__device__ __constant__ int   c_ST[4] = {0, 16700, 20900, 21950};

// ---------------- Scratch (device globals; no allocation allowed) ---------
__device__ float g_value[(size_t)TOTQ * 256];    // (n*LEN_IN, m*32+d)
__device__ float g_off  [(size_t)TOTQ * 256];    // (q, m*32 + l*8 + p*2 + c)
__device__ float g_attn [(size_t)TOTQ * 128];    // (q, m*16 + l*4 + p) logits
__device__ float g_head [(size_t)TOTQ * 256];    // (q, m*32 + d)

// ---------------- SGEMM: C = A @ B + bias  (fp32) -------------------------
// 128x128 block tile, K-tile 8, 256 threads, 8x8 microtile.
// dstSel selects destination among device globals / external out.
// srcSel selects A among external / g_head.
#define BM 128
#define BN 128
#define BK 8

__global__ __launch_bounds__(256, 2)
void sgemm_bias(const float* __restrict__ Aext,
                const float* __restrict__ B,
                const float* __restrict__ bias,
                float* __restrict__ Cext,
                int M, int N, int K,
                int srcSel, int dstSel)
{
    const float* A = (srcSel == 0) ? Aext : g_head;
    float* C;
    switch (dstSel) {
        case 0: C = g_value; break;
        case 1: C = g_off;   break;
        case 2: C = g_attn;  break;
        default: C = Cext;   break;
    }

    __shared__ float As[BK][BM];
    __shared__ float Bs[BK][BN];

    const int tid = threadIdx.x;
    const int bm = blockIdx.y * BM;
    const int bn = blockIdx.x * BN;
    const int tx = tid & 15;        // 0..15 -> col group
    const int ty = tid >> 4;        // 0..15 -> row group

    float acc[8][8];
    #pragma unroll
    for (int i = 0; i < 8; i++)
        #pragma unroll
        for (int j = 0; j < 8; j++) acc[i][j] = 0.f;

    const int a_row  = tid >> 1;          // 0..127
    const int a_col4 = (tid & 1) * 4;     // 0 or 4
    const int b_row  = tid >> 5;          // 0..7
    const int b_col4 = (tid & 31) * 4;    // 0..124

    for (int kt = 0; kt < K; kt += BK) {
        // Load A tile (guard rows), store transposed As[k][row]
        float4 av = make_float4(0.f, 0.f, 0.f, 0.f);
        const int gr = bm + a_row;
        if (gr < M)
            av = *reinterpret_cast<const float4*>(&A[(size_t)gr * K + kt + a_col4]);
        As[a_col4 + 0][a_row] = av.x;
        As[a_col4 + 1][a_row] = av.y;
        As[a_col4 + 2][a_row] = av.z;
        As[a_col4 + 3][a_row] = av.w;
        // Load B tile
        float4 bv = *reinterpret_cast<const float4*>(
            &B[(size_t)(kt + b_row) * N + bn + b_col4]);
        *reinterpret_cast<float4*>(&Bs[b_row][b_col4]) = bv;
        __syncthreads();

        #pragma unroll
        for (int k = 0; k < BK; k++) {
            float4 a0 = *reinterpret_cast<float4*>(&As[k][ty * 8]);
            float4 a1 = *reinterpret_cast<float4*>(&As[k][ty * 8 + 4]);
            float4 b0 = *reinterpret_cast<float4*>(&Bs[k][tx * 8]);
            float4 b1 = *reinterpret_cast<float4*>(&Bs[k][tx * 8 + 4]);
            float a[8] = {a0.x, a0.y, a0.z, a0.w, a1.x, a1.y, a1.z, a1.w};
            float b[8] = {b0.x, b0.y, b0.z, b0.w, b1.x, b1.y, b1.z, b1.w};
            #pragma unroll
            for (int i = 0; i < 8; i++)
                #pragma unroll
                for (int j = 0; j < 8; j++)
                    acc[i][j] = fmaf(a[i], b[j], acc[i][j]);
        }
        __syncthreads();
    }

    // Epilogue: add bias, store (row-guarded)
    #pragma unroll
    for (int i = 0; i < 8; i++) {
        const int row = bm + ty * 8 + i;
        if (row >= M) continue;
        #pragma unroll
        for (int jq = 0; jq < 2; jq++) {
            const int col = bn + tx * 8 + jq * 4;
            float4 o;
            o.x = acc[i][jq * 4 + 0] + bias[col + 0];
            o.y = acc[i][jq * 4 + 1] + bias[col + 1];
            o.z = acc[i][jq * 4 + 2] + bias[col + 2];
            o.w = acc[i][jq * 4 + 3] + bias[col + 3];
            *reinterpret_cast<float4*>(&C[(size_t)row * N + col]) = o;
        }
    }
}

// ---------------- Sampling kernel -----------------------------------------
// One block (256 threads) per query. Warp = head, lane = channel.
// Softmax over 16 logits per head, then 16 bilinear-sampled points.
__global__ __launch_bounds__(256)
void msda_sample(const float* __restrict__ ref)
{
    const int q    = blockIdx.x;          // 0..TOTQ-1
    const int m    = threadIdx.x >> 5;    // head
    const int lane = threadIdx.x & 31;    // channel d
    const int n    = q / LEN_IN;

    // ---- softmax over the 16 attention logits of this head ----
    float logit = -1e30f;
    if (lane < 16) logit = g_attn[(size_t)q * 128 + m * 16 + lane];
    float mx = logit;
    #pragma unroll
    for (int s = 16; s >= 1; s >>= 1)
        mx = fmaxf(mx, __shfl_xor_sync(0xffffffffu, mx, s));
    float e = (lane < 16) ? __expf(logit - mx) : 0.f;
    float sum = e;
    #pragma unroll
    for (int s = 16; s >= 1; s >>= 1)
        sum += __shfl_xor_sync(0xffffffffu, sum, s);
    const float wattn = e / sum;          // valid for lane < 16

    // each lane holds one of the 32 offset values of this head
    const float offv = g_off[(size_t)q * 256 + m * 32 + lane];

    float acc = 0.f;
    const float* vbase = g_value + (size_t)n * LEN_IN * 256 + m * 32 + lane;

    #pragma unroll
    for (int l = 0; l < N_LEVELS; l++) {
        const int   Wi = c_W[l], Hi = c_H[l];
        const float Wf = (float)Wi, Hf = (float)Hi;
        const float rx = ref[((size_t)q * 4 + l) * 2 + 0];
        const float ry = ref[((size_t)q * 4 + l) * 2 + 1];
        const float* vlev = vbase + (size_t)c_ST[l] * 256;

        #pragma unroll
        for (int p = 0; p < N_POINTS; p++) {
            const float w_lp = __shfl_sync(0xffffffffu, wattn, l * 4 + p);
            const float ox   = __shfl_sync(0xffffffffu, offv, l * 8 + p * 2);
            const float oy   = __shfl_sync(0xffffffffu, offv, l * 8 + p * 2 + 1);

            // x = (rx + ox/W)*W - 0.5 = rx*W + ox - 0.5
            const float x = fmaf(rx, Wf, ox) - 0.5f;
            const float y = fmaf(ry, Hf, oy) - 0.5f;
            const float x0f = floorf(x);
            const float y0f = floorf(y);
            const float lx = x - x0f;
            const float ly = y - y0f;
            const int x0 = (int)x0f;
            const int y0 = (int)y0f;

            const float w00 = (1.f - lx) * (1.f - ly) * w_lp;
            const float w01 = lx * (1.f - ly) * w_lp;
            const float w10 = (1.f - lx) * ly * w_lp;
            const float w11 = lx * ly * w_lp;

            const bool xv0 = (x0 >= 0) && (x0 < Wi);
            const bool xv1 = (x0 + 1 >= 0) && (x0 + 1 < Wi);
            const bool yv0 = (y0 >= 0) && (y0 < Hi);
            const bool yv1 = (y0 + 1 >= 0) && (y0 + 1 < Hi);

            if (yv0) {
                const float* r0 = vlev + (size_t)y0 * Wi * 256;
                if (xv0) acc = fmaf(r0[(size_t)x0 * 256],       w00, acc);
                if (xv1) acc = fmaf(r0[(size_t)(x0 + 1) * 256], w01, acc);
            }
            if (yv1) {
                const float* r1 = vlev + (size_t)(y0 + 1) * Wi * 256;
                if (xv0) acc = fmaf(r1[(size_t)x0 * 256],       w10, acc);
                if (xv1) acc = fmaf(r1[(size_t)(x0 + 1) * 256], w11, acc);
            }
        }
    }

    g_head[(size_t)q * 256 + m * 32 + lane] = acc;
}

// ---------------- Launch --------------------------------------------------
extern "C" void kernel_launch(void* const* d_in, const int* in_sizes, int n_in,
                              void* d_out, int out_size)
{
    const float* query   = (const float*)d_in[0];
    const float* refpts  = (const float*)d_in[1];
    const float* inflat  = (const float*)d_in[2];
    // d_in[3] = spatial_shapes (compile-time constants), d_in[4] = level starts
    const float* w_value = (const float*)d_in[5];
    const float* b_value = (const float*)d_in[6];
    const float* w_off   = (const float*)d_in[7];
    const float* b_off   = (const float*)d_in[8];
    const float* w_attn  = (const float*)d_in[9];
    const float* b_attn  = (const float*)d_in[10];
    const float* w_out   = (const float*)d_in[11];
    const float* b_out   = (const float*)d_in[12];
    float* out = (float*)d_out;

    const int M = TOTQ;                       // 44446
    const dim3 blk(256);
    const int mblocks = (M + BM - 1) / BM;    // 348

    // value = input_flatten @ w_value + b_value     -> g_value
    sgemm_bias<<<dim3(256 / BN, mblocks), blk>>>(inflat, w_value, b_value, nullptr,
                                                 M, 256, 256, 0, 0);
    // off = query @ w_off + b_off                   -> g_off
    sgemm_bias<<<dim3(256 / BN, mblocks), blk>>>(query, w_off, b_off, nullptr,
                                                 M, 256, 256, 0, 1);
    // attn logits = query @ w_attn + b_attn         -> g_attn
    sgemm_bias<<<dim3(128 / BN, mblocks), blk>>>(query, w_attn, b_attn, nullptr,
                                                 M, 128, 256, 0, 2);
    // softmax + bilinear sampling                   -> g_head
    msda_sample<<<TOTQ, 256>>>(refpts);
    // out = g_head @ w_out + b_out                  -> d_out
    sgemm_bias<<<dim3(256 / BN, mblocks), blk>>>(nullptr, w_out, b_out, out,
                                                 M, 256, 256, 1, 3);
}

// round 2
// speedup vs baseline: 1.3008x; 1.3008x over previous
#include <cuda_runtime.h>
#include <cstdint>

// ---------------- Problem constants (fixed by the dataset) ----------------
#define D_MODEL   256
#define N_HEADS   8
#define HEAD_DIM  32
#define N_LEVELS  4
#define N_POINTS  4
#define LEN_IN    22223
#define NBATCH    2
#define TOTQ      (NBATCH * LEN_IN)   // 44446

__device__ __constant__ int   c_W[4] = {167, 84, 42, 21};
__device__ __constant__ int   c_H[4] = {100, 50, 25, 13};
__device__ __constant__ int   c_ST[4] = {0, 16700, 20900, 21950};

// ---------------- Scratch (device globals; no allocation allowed) ---------
__device__ float g_value[(size_t)TOTQ * 256];    // (n*LEN_IN, m*32+d)
__device__ float g_off  [(size_t)TOTQ * 256];    // (q, m*32 + l*8 + p*2 + c)
__device__ float g_attn [(size_t)TOTQ * 128];    // (q, m*16 + l*4 + p) logits
__device__ float g_head [(size_t)TOTQ * 256];    // (q, m*32 + d)

// ---------------- SGEMM: C = A @ B + bias  (fp32) -------------------------
#define BM 128
#define BN 128
#define BK 8

__global__ __launch_bounds__(256, 2)
void sgemm_bias(const float* __restrict__ Aext,
                const float* __restrict__ B,
                const float* __restrict__ bias,
                float* __restrict__ Cext,
                int M, int N, int K,
                int srcSel, int dstSel)
{
    const float* A = (srcSel == 0) ? Aext : g_head;
    float* C;
    switch (dstSel) {
        case 0: C = g_value; break;
        case 1: C = g_off;   break;
        case 2: C = g_attn;  break;
        default: C = Cext;   break;
    }

    __shared__ float As[BK][BM];
    __shared__ float Bs[BK][BN];

    const int tid = threadIdx.x;
    const int bm = blockIdx.y * BM;
    const int bn = blockIdx.x * BN;
    const int tx = tid & 15;
    const int ty = tid >> 4;

    float acc[8][8];
    #pragma unroll
    for (int i = 0; i < 8; i++)
        #pragma unroll
        for (int j = 0; j < 8; j++) acc[i][j] = 0.f;

    const int a_row  = tid >> 1;
    const int a_col4 = (tid & 1) * 4;
    const int b_row  = tid >> 5;
    const int b_col4 = (tid & 31) * 4;

    for (int kt = 0; kt < K; kt += BK) {
        float4 av = make_float4(0.f, 0.f, 0.f, 0.f);
        const int gr = bm + a_row;
        if (gr < M)
            av = *reinterpret_cast<const float4*>(&A[(size_t)gr * K + kt + a_col4]);
        As[a_col4 + 0][a_row] = av.x;
        As[a_col4 + 1][a_row] = av.y;
        As[a_col4 + 2][a_row] = av.z;
        As[a_col4 + 3][a_row] = av.w;
        float4 bv = *reinterpret_cast<const float4*>(
            &B[(size_t)(kt + b_row) * N + bn + b_col4]);
        *reinterpret_cast<float4*>(&Bs[b_row][b_col4]) = bv;
        __syncthreads();

        #pragma unroll
        for (int k = 0; k < BK; k++) {
            float4 a0 = *reinterpret_cast<float4*>(&As[k][ty * 8]);
            float4 a1 = *reinterpret_cast<float4*>(&As[k][ty * 8 + 4]);
            float4 b0 = *reinterpret_cast<float4*>(&Bs[k][tx * 8]);
            float4 b1 = *reinterpret_cast<float4*>(&Bs[k][tx * 8 + 4]);
            float a[8] = {a0.x, a0.y, a0.z, a0.w, a1.x, a1.y, a1.z, a1.w};
            float b[8] = {b0.x, b0.y, b0.z, b0.w, b1.x, b1.y, b1.z, b1.w};
            #pragma unroll
            for (int i = 0; i < 8; i++)
                #pragma unroll
                for (int j = 0; j < 8; j++)
                    acc[i][j] = fmaf(a[i], b[j], acc[i][j]);
        }
        __syncthreads();
    }

    #pragma unroll
    for (int i = 0; i < 8; i++) {
        const int row = bm + ty * 8 + i;
        if (row >= M) continue;
        #pragma unroll
        for (int jq = 0; jq < 2; jq++) {
            const int col = bn + tx * 8 + jq * 4;
            float4 o;
            o.x = acc[i][jq * 4 + 0] + bias[col + 0];
            o.y = acc[i][jq * 4 + 1] + bias[col + 1];
            o.z = acc[i][jq * 4 + 2] + bias[col + 2];
            o.w = acc[i][jq * 4 + 3] + bias[col + 3];
            *reinterpret_cast<float4*>(&C[(size_t)row * N + col]) = o;
        }
    }
}

// ---------------- Sampling kernel (float4-vectorized) ---------------------
// Warp = 4 heads (8 lanes/head, float4 per lane). 2 warps per query.
// Block = 256 threads = 8 warps = 4 queries.
__global__ __launch_bounds__(256)
void msda_sample(const float* __restrict__ ref)
{
    const int warpGlobal = blockIdx.x * 8 + (threadIdx.x >> 5);
    if (warpGlobal >= TOTQ * 2) return;
    const int q        = warpGlobal >> 1;       // query
    const int headBase = (warpGlobal & 1) * 4;  // 0 or 4
    const int lane     = threadIdx.x & 31;
    const int sub      = lane >> 3;             // which head in warp (0..3)
    const int j        = lane & 7;              // channel quad (0..7)
    const int m        = headBase + sub;        // head
    const int n        = q / LEN_IN;

    // ---- softmax over 16 logits of head m; lane j holds points j and j+8 --
    const float la = g_attn[(size_t)q * 128 + m * 16 + j];
    const float lb = g_attn[(size_t)q * 128 + m * 16 + 8 + j];
    float mx = fmaxf(la, lb);
    #pragma unroll
    for (int s = 4; s >= 1; s >>= 1)
        mx = fmaxf(mx, __shfl_xor_sync(0xffffffffu, mx, s, 8));
    float ea = __expf(la - mx);
    float eb = __expf(lb - mx);
    float sum = ea + eb;
    #pragma unroll
    for (int s = 4; s >= 1; s >>= 1)
        sum += __shfl_xor_sync(0xffffffffu, sum, s, 8);
    const float inv = 1.f / sum;
    const float wa = ea * inv;   // weight for point j
    const float wb = eb * inv;   // weight for point j+8

    // ---- offsets: lane j holds float4 = offsets[4j..4j+3] = points 2j,2j+1
    const float4 off = *reinterpret_cast<const float4*>(
        &g_off[(size_t)q * 256 + m * 32 + j * 4]);

    // ---- reference points for this query (8 floats, L1-resident) ----------
    float4 acc = make_float4(0.f, 0.f, 0.f, 0.f);
    const float* vbase = g_value + (size_t)n * LEN_IN * 256 + m * 32 + j * 4;

    #pragma unroll
    for (int l = 0; l < N_LEVELS; l++) {
        const int   Wi = c_W[l], Hi = c_H[l];
        const float Wf = (float)Wi, Hf = (float)Hi;
        const float2 r = *reinterpret_cast<const float2*>(&ref[((size_t)q * 4 + l) * 2]);
        const float* vlev = vbase + (size_t)c_ST[l] * 256;

        #pragma unroll
        for (int p = 0; p < N_POINTS; p++) {
            const int pt = l * 4 + p;                 // 0..15
            // attention weight of point pt (segment-wide shuffle, width 8)
            const float w_lp = __shfl_sync(0xffffffffu,
                                           (pt < 8) ? wa : wb, pt & 7, 8);
            // offsets of point pt: lane pt>>1, components (pt&1)*2, +1
            const float ox = __shfl_sync(0xffffffffu,
                                         (pt & 1) ? off.z : off.x, pt >> 1, 8);
            const float oy = __shfl_sync(0xffffffffu,
                                         (pt & 1) ? off.w : off.y, pt >> 1, 8);

            const float x = fmaf(r.x, Wf, ox) - 0.5f;
            const float y = fmaf(r.y, Hf, oy) - 0.5f;
            const float x0f = floorf(x);
            const float y0f = floorf(y);
            const float lx = x - x0f;
            const float ly = y - y0f;
            const int x0 = (int)x0f;
            const int y0 = (int)y0f;

            const float w00 = (1.f - lx) * (1.f - ly) * w_lp;
            const float w01 = lx * (1.f - ly) * w_lp;
            const float w10 = (1.f - lx) * ly * w_lp;
            const float w11 = lx * ly * w_lp;

            const bool xv0 = (x0 >= 0) && (x0 < Wi);
            const bool xv1 = (x0 + 1 >= 0) && (x0 + 1 < Wi);
            const bool yv0 = (y0 >= 0) && (y0 < Hi);
            const bool yv1 = (y0 + 1 >= 0) && (y0 + 1 < Hi);

            if (yv0) {
                const float* r0 = vlev + (size_t)y0 * Wi * 256;
                if (xv0) {
                    const float4 v = *reinterpret_cast<const float4*>(&r0[(size_t)x0 * 256]);
                    acc.x = fmaf(v.x, w00, acc.x); acc.y = fmaf(v.y, w00, acc.y);
                    acc.z = fmaf(v.z, w00, acc.z); acc.w = fmaf(v.w, w00, acc.w);
                }
                if (xv1) {
                    const float4 v = *reinterpret_cast<const float4*>(&r0[(size_t)(x0 + 1) * 256]);
                    acc.x = fmaf(v.x, w01, acc.x); acc.y = fmaf(v.y, w01, acc.y);
                    acc.z = fmaf(v.z, w01, acc.z); acc.w = fmaf(v.w, w01, acc.w);
                }
            }
            if (yv1) {
                const float* r1 = vlev + (size_t)(y0 + 1) * Wi * 256;
                if (xv0) {
                    const float4 v = *reinterpret_cast<const float4*>(&r1[(size_t)x0 * 256]);
                    acc.x = fmaf(v.x, w10, acc.x); acc.y = fmaf(v.y, w10, acc.y);
                    acc.z = fmaf(v.z, w10, acc.z); acc.w = fmaf(v.w, w10, acc.w);
                }
                if (xv1) {
                    const float4 v = *reinterpret_cast<const float4*>(&r1[(size_t)(x0 + 1) * 256]);
                    acc.x = fmaf(v.x, w11, acc.x); acc.y = fmaf(v.y, w11, acc.y);
                    acc.z = fmaf(v.z, w11, acc.z); acc.w = fmaf(v.w, w11, acc.w);
                }
            }
        }
    }

    *reinterpret_cast<float4*>(&g_head[(size_t)q * 256 + m * 32 + j * 4]) = acc;
}

// ---------------- Launch --------------------------------------------------
extern "C" void kernel_launch(void* const* d_in, const int* in_sizes, int n_in,
                              void* d_out, int out_size)
{
    const float* query   = (const float*)d_in[0];
    const float* refpts  = (const float*)d_in[1];
    const float* inflat  = (const float*)d_in[2];
    const float* w_value = (const float*)d_in[5];
    const float* b_value = (const float*)d_in[6];
    const float* w_off   = (const float*)d_in[7];
    const float* b_off   = (const float*)d_in[8];
    const float* w_attn  = (const float*)d_in[9];
    const float* b_attn  = (const float*)d_in[10];
    const float* w_out   = (const float*)d_in[11];
    const float* b_out   = (const float*)d_in[12];
    float* out = (float*)d_out;

    const int M = TOTQ;
    const dim3 blk(256);
    const int mblocks = (M + BM - 1) / BM;

    sgemm_bias<<<dim3(256 / BN, mblocks), blk>>>(inflat, w_value, b_value, nullptr,
                                                 M, 256, 256, 0, 0);
    sgemm_bias<<<dim3(256 / BN, mblocks), blk>>>(query, w_off, b_off, nullptr,
                                                 M, 256, 256, 0, 1);
    sgemm_bias<<<dim3(128 / BN, mblocks), blk>>>(query, w_attn, b_attn, nullptr,
                                                 M, 128, 256, 0, 2);

    const int nwarps  = TOTQ * 2;
    const int nblocks = (nwarps + 7) / 8;
    msda_sample<<<nblocks, 256>>>(refpts);

    sgemm_bias<<<dim3(256 / BN, mblocks), blk>>>(nullptr, w_out, b_out, out,
                                                 M, 256, 256, 1, 3);
}

// round 5
// speedup vs baseline: 2.3185x; 1.7824x over previous
#include <cuda_runtime.h>
#include <cuda_bf16.h>
#include <cstdint>

// ---------------- Problem constants (fixed by the dataset) ----------------
#define D_MODEL   256
#define N_HEADS   8
#define HEAD_DIM  32
#define N_LEVELS  4
#define N_POINTS  4
#define LEN_IN    22223
#define NBATCH    2
#define TOTQ      (NBATCH * LEN_IN)   // 44446

__device__ __constant__ int   c_W[4] = {167, 84, 42, 21};
__device__ __constant__ int   c_H[4] = {100, 50, 25, 13};
__device__ __constant__ int   c_ST[4] = {0, 16700, 20900, 21950};

// ---------------- Scratch (device globals; no allocation allowed) ---------
__device__ float g_value[(size_t)TOTQ * 256];
__device__ float g_off  [(size_t)TOTQ * 256];
__device__ float g_attn [(size_t)TOTQ * 128];
__device__ float g_head [(size_t)TOTQ * 256];
// split-bf16 weights, [n][k] row-major (k contiguous, 256 per row)
// [0,65536)=w_value  [65536,131072)=w_off  [131072,163840)=w_attn  [163840,229376)=w_out
__device__ __nv_bfloat16 g_bhi[229376];
__device__ __nv_bfloat16 g_blo[229376];

// ---------------- helpers ---------------------------------------------------
__device__ __forceinline__ uint32_t smem_u32(const void* p) {
    uint32_t a;
    asm("{ .reg .u64 t; cvta.to.shared.u64 t, %1; cvt.u32.u64 %0, t; }" : "=r"(a) : "l"(p));
    return a;
}
__device__ __forceinline__ void split2(float a, float b, uint32_t& hi, uint32_t& lo) {
    const __nv_bfloat16 ha = __float2bfloat16(a);
    const __nv_bfloat16 hb = __float2bfloat16(b);
    hi = ((uint32_t)__bfloat16_as_ushort(hb) << 16) | __bfloat16_as_ushort(ha);
    const __nv_bfloat16 la = __float2bfloat16(a - __bfloat162float(ha));
    const __nv_bfloat16 lb = __float2bfloat16(b - __bfloat162float(hb));
    lo = ((uint32_t)__bfloat16_as_ushort(lb) << 16) | __bfloat16_as_ushort(la);
}

__device__ __forceinline__ void ldm_x4(uint32_t* r, uint32_t addr) {
    asm volatile("ldmatrix.sync.aligned.m8n8.x4.shared.b16 {%0,%1,%2,%3}, [%4];"
                 : "=r"(r[0]), "=r"(r[1]), "=r"(r[2]), "=r"(r[3]) : "r"(addr));
}
__device__ __forceinline__ void mma_bf16(float* d, const uint32_t* a, uint32_t b0, uint32_t b1) {
    asm volatile(
        "mma.sync.aligned.m16n8k16.row.col.f32.bf16.bf16.f32 "
        "{%0,%1,%2,%3}, {%4,%5,%6,%7}, {%8,%9}, {%0,%1,%2,%3};"
        : "+f"(d[0]), "+f"(d[1]), "+f"(d[2]), "+f"(d[3])
        : "r"(a[0]), "r"(a[1]), "r"(a[2]), "r"(a[3]), "r"(b0), "r"(b1));
}

// ---------------- Weight prep: transpose + bf16 hi/lo split ----------------
__global__ void prep_weights(const float* __restrict__ wv, const float* __restrict__ wo,
                             const float* __restrict__ wa, const float* __restrict__ wu)
{
    const int idx = blockIdx.x * 256 + threadIdx.x;
    if (idx >= 229376) return;
    float a;
    if (idx < 65536)       { int l = idx;          int n = l >> 8, k = l & 255; a = wv[k * 256 + n]; }
    else if (idx < 131072) { int l = idx - 65536;  int n = l >> 8, k = l & 255; a = wo[k * 256 + n]; }
    else if (idx < 163840) { int l = idx - 131072; int n = l >> 8, k = l & 255; a = wa[k * 128 + n]; }
    else                   { int l = idx - 163840; int n = l >> 8, k = l & 255; a = wu[k * 256 + n]; }
    const __nv_bfloat16 h = __float2bfloat16(a);
    g_bhi[idx] = h;
    g_blo[idx] = __float2bfloat16(a - __bfloat162float(h));
}

// ---------------- HMMA GEMM: C = A(fp32) @ W + bias ------------------------
// 128x128 CTA tile, BK=32, 8 warps (4m x 2n), warp tile 32x64, m16n8k16.
// 3-pass split bf16: ah*bh + al*bh + ah*bl.
#define SROW 80   // smem row stride (bytes) for 32 bf16 + pad (conflict-free)

__global__ __launch_bounds__(256, 2)
void hmma_gemm(const float* __restrict__ Aext,
               const float* __restrict__ bias,
               float* __restrict__ Cext,
               int M, int N, int srcSel, int sel)
{
    __shared__ __align__(16) uint8_t sAh[128 * SROW];
    __shared__ __align__(16) uint8_t sAl[128 * SROW];
    __shared__ __align__(16) uint8_t sBh[128 * SROW];
    __shared__ __align__(16) uint8_t sBl[128 * SROW];

    const int tid  = threadIdx.x;
    const int wid  = tid >> 5;
    const int lane = tid & 31;
    const int bm   = blockIdx.y * 128;
    const int bn   = blockIdx.x * 128;
    const int warp_m = wid & 3;       // 0..3 -> 32 rows each
    const int warp_n = wid >> 2;      // 0..1 -> 64 cols each

    const float* A = (srcSel == 0) ? Aext : g_head;
    const int boffs[4] = {0, 65536, 131072, 163840};
    const __nv_bfloat16* Bhi = g_bhi + boffs[sel];
    const __nv_bfloat16* Blo = g_blo + boffs[sel];
    float* C;
    switch (sel) {
        case 0: C = g_value; break;
        case 1: C = g_off;   break;
        case 2: C = g_attn;  break;
        default: C = Cext;   break;
    }

    const uint32_t sAh32 = smem_u32(sAh);
    const uint32_t sAl32 = smem_u32(sAl);

    float acc[2][8][4];
    #pragma unroll
    for (int i = 0; i < 2; i++)
        #pragma unroll
        for (int j = 0; j < 8; j++)
            #pragma unroll
            for (int k = 0; k < 4; k++) acc[i][j][k] = 0.f;

    // A load mapping: row = tid>>1 (0..127), k-seg = (tid&1)*16
    const int arow = tid >> 1;
    const int akseg = (tid & 1) * 16;
    const int gr = bm + arow;

    #pragma unroll 1
    for (int c = 0; c < 8; c++) {
        const int k0 = c * 32;

        // ---- global loads into registers (overlap with previous compute) ----
        float4 f[4];
        if (gr < M) {
            const float4* s = reinterpret_cast<const float4*>(A + (size_t)gr * 256 + k0 + akseg);
            f[0] = s[0]; f[1] = s[1]; f[2] = s[2]; f[3] = s[3];
        } else {
            f[0] = f[1] = f[2] = f[3] = make_float4(0.f, 0.f, 0.f, 0.f);
        }
        uint4 bhv[2], blv[2];
        int bn_[2], bseg_[2];
        #pragma unroll
        for (int i = 0; i < 2; i++) {
            const int idx = i * 256 + tid;          // 0..511
            const int n   = idx >> 2;               // 0..127
            const int seg = idx & 3;                // 0..3 (8 bf16 each)
            bn_[i] = n; bseg_[i] = seg;
            const size_t go = (size_t)(bn + n) * 256 + k0 + seg * 8;
            bhv[i] = *reinterpret_cast<const uint4*>(Bhi + go);
            blv[i] = *reinterpret_cast<const uint4*>(Blo + go);
        }

        __syncthreads();   // previous iteration's MMAs done with smem

        // ---- store A (split) ----
        {
            uint32_t hp[8], lp[8];
            split2(f[0].x, f[0].y, hp[0], lp[0]);
            split2(f[0].z, f[0].w, hp[1], lp[1]);
            split2(f[1].x, f[1].y, hp[2], lp[2]);
            split2(f[1].z, f[1].w, hp[3], lp[3]);
            split2(f[2].x, f[2].y, hp[4], lp[4]);
            split2(f[2].z, f[2].w, hp[5], lp[5]);
            split2(f[3].x, f[3].y, hp[6], lp[6]);
            split2(f[3].z, f[3].w, hp[7], lp[7]);
            const int off = arow * SROW + akseg * 2;
            *reinterpret_cast<uint4*>(sAh + off)      = make_uint4(hp[0], hp[1], hp[2], hp[3]);
            *reinterpret_cast<uint4*>(sAh + off + 16) = make_uint4(hp[4], hp[5], hp[6], hp[7]);
            *reinterpret_cast<uint4*>(sAl + off)      = make_uint4(lp[0], lp[1], lp[2], lp[3]);
            *reinterpret_cast<uint4*>(sAl + off + 16) = make_uint4(lp[4], lp[5], lp[6], lp[7]);
        }
        // ---- store B ----
        #pragma unroll
        for (int i = 0; i < 2; i++) {
            const int off = bn_[i] * SROW + bseg_[i] * 16;
            *reinterpret_cast<uint4*>(sBh + off) = bhv[i];
            *reinterpret_cast<uint4*>(sBl + off) = blv[i];
        }
        __syncthreads();

        // ---- compute: 2 k16-steps ----
        #pragma unroll
        for (int ks = 0; ks < 2; ks++) {
            uint32_t ah[2][4], al[2][4];
            #pragma unroll
            for (int ma = 0; ma < 2; ma++) {
                const uint32_t ao = (uint32_t)((warp_m * 32 + ma * 16 + (lane & 15)) * SROW
                                               + ks * 32 + (lane >> 4) * 16);
                ldm_x4(ah[ma], sAh32 + ao);
                ldm_x4(al[ma], sAl32 + ao);
            }
            #pragma unroll
            for (int na = 0; na < 8; na++) {
                const int boff = (warp_n * 64 + na * 8 + (lane >> 2)) * SROW
                                 + ks * 32 + (lane & 3) * 4;
                const uint32_t bh0 = *reinterpret_cast<const uint32_t*>(sBh + boff);
                const uint32_t bh1 = *reinterpret_cast<const uint32_t*>(sBh + boff + 16);
                const uint32_t bl0 = *reinterpret_cast<const uint32_t*>(sBl + boff);
                const uint32_t bl1 = *reinterpret_cast<const uint32_t*>(sBl + boff + 16);
                #pragma unroll
                for (int ma = 0; ma < 2; ma++) {
                    mma_bf16(acc[ma][na], ah[ma], bh0, bh1);
                    mma_bf16(acc[ma][na], al[ma], bh0, bh1);
                    mma_bf16(acc[ma][na], ah[ma], bl0, bl1);
                }
            }
        }
    }

    // ---- epilogue: bias + store ----
    #pragma unroll
    for (int ma = 0; ma < 2; ma++) {
        const int row0 = bm + warp_m * 32 + ma * 16 + (lane >> 2);
        const int row1 = row0 + 8;
        #pragma unroll
        for (int na = 0; na < 8; na++) {
            const int col = bn + warp_n * 64 + na * 8 + 2 * (lane & 3);
            const float2 bv = *reinterpret_cast<const float2*>(bias + col);
            if (row0 < M) {
                float2 o = make_float2(acc[ma][na][0] + bv.x, acc[ma][na][1] + bv.y);
                *reinterpret_cast<float2*>(&C[(size_t)row0 * N + col]) = o;
            }
            if (row1 < M) {
                float2 o = make_float2(acc[ma][na][2] + bv.x, acc[ma][na][3] + bv.y);
                *reinterpret_cast<float2*>(&C[(size_t)row1 * N + col]) = o;
            }
        }
    }
}

// ---------------- Sampling kernel (float4-vectorized; unchanged) ----------
__global__ __launch_bounds__(256)
void msda_sample(const float* __restrict__ ref)
{
    const int warpGlobal = blockIdx.x * 8 + (threadIdx.x >> 5);
    if (warpGlobal >= TOTQ * 2) return;
    const int q        = warpGlobal >> 1;
    const int headBase = (warpGlobal & 1) * 4;
    const int lane     = threadIdx.x & 31;
    const int sub      = lane >> 3;
    const int j        = lane & 7;
    const int m        = headBase + sub;
    const int n        = q / LEN_IN;

    const float la = g_attn[(size_t)q * 128 + m * 16 + j];
    const float lb = g_attn[(size_t)q * 128 + m * 16 + 8 + j];
    float mx = fmaxf(la, lb);
    #pragma unroll
    for (int s = 4; s >= 1; s >>= 1)
        mx = fmaxf(mx, __shfl_xor_sync(0xffffffffu, mx, s, 8));
    float ea = __expf(la - mx);
    float eb = __expf(lb - mx);
    float sum = ea + eb;
    #pragma unroll
    for (int s = 4; s >= 1; s >>= 1)
        sum += __shfl_xor_sync(0xffffffffu, sum, s, 8);
    const float inv = 1.f / sum;
    const float wa = ea * inv;
    const float wb = eb * inv;

    const float4 off = *reinterpret_cast<const float4*>(
        &g_off[(size_t)q * 256 + m * 32 + j * 4]);

    float4 acc = make_float4(0.f, 0.f, 0.f, 0.f);
    const float* vbase = g_value + (size_t)n * LEN_IN * 256 + m * 32 + j * 4;

    #pragma unroll
    for (int l = 0; l < N_LEVELS; l++) {
        const int   Wi = c_W[l], Hi = c_H[l];
        const float Wf = (float)Wi, Hf = (float)Hi;
        const float2 r = *reinterpret_cast<const float2*>(&ref[((size_t)q * 4 + l) * 2]);
        const float* vlev = vbase + (size_t)c_ST[l] * 256;

        #pragma unroll
        for (int p = 0; p < N_POINTS; p++) {
            const int pt = l * 4 + p;
            const float w_lp = __shfl_sync(0xffffffffu, (pt < 8) ? wa : wb, pt & 7, 8);
            const float ox = __shfl_sync(0xffffffffu, (pt & 1) ? off.z : off.x, pt >> 1, 8);
            const float oy = __shfl_sync(0xffffffffu, (pt & 1) ? off.w : off.y, pt >> 1, 8);

            const float x = fmaf(r.x, Wf, ox) - 0.5f;
            const float y = fmaf(r.y, Hf, oy) - 0.5f;
            const float x0f = floorf(x);
            const float y0f = floorf(y);
            const float lx = x - x0f;
            const float ly = y - y0f;
            const int x0 = (int)x0f;
            const int y0 = (int)y0f;

            const float w00 = (1.f - lx) * (1.f - ly) * w_lp;
            const float w01 = lx * (1.f - ly) * w_lp;
            const float w10 = (1.f - lx) * ly * w_lp;
            const float w11 = lx * ly * w_lp;

            const bool xv0 = (x0 >= 0) && (x0 < Wi);
            const bool xv1 = (x0 + 1 >= 0) && (x0 + 1 < Wi);
            const bool yv0 = (y0 >= 0) && (y0 < Hi);
            const bool yv1 = (y0 + 1 >= 0) && (y0 + 1 < Hi);

            if (yv0) {
                const float* r0 = vlev + (size_t)y0 * Wi * 256;
                if (xv0) {
                    const float4 v = *reinterpret_cast<const float4*>(&r0[(size_t)x0 * 256]);
                    acc.x = fmaf(v.x, w00, acc.x); acc.y = fmaf(v.y, w00, acc.y);
                    acc.z = fmaf(v.z, w00, acc.z); acc.w = fmaf(v.w, w00, acc.w);
                }
                if (xv1) {
                    const float4 v = *reinterpret_cast<const float4*>(&r0[(size_t)(x0 + 1) * 256]);
                    acc.x = fmaf(v.x, w01, acc.x); acc.y = fmaf(v.y, w01, acc.y);
                    acc.z = fmaf(v.z, w01, acc.z); acc.w = fmaf(v.w, w01, acc.w);
                }
            }
            if (yv1) {
                const float* r1 = vlev + (size_t)(y0 + 1) * Wi * 256;
                if (xv0) {
                    const float4 v = *reinterpret_cast<const float4*>(&r1[(size_t)x0 * 256]);
                    acc.x = fmaf(v.x, w10, acc.x); acc.y = fmaf(v.y, w10, acc.y);
                    acc.z = fmaf(v.z, w10, acc.z); acc.w = fmaf(v.w, w10, acc.w);
                }
                if (xv1) {
                    const float4 v = *reinterpret_cast<const float4*>(&r1[(size_t)(x0 + 1) * 256]);
                    acc.x = fmaf(v.x, w11, acc.x); acc.y = fmaf(v.y, w11, acc.y);
                    acc.z = fmaf(v.z, w11, acc.z); acc.w = fmaf(v.w, w11, acc.w);
                }
            }
        }
    }

    *reinterpret_cast<float4*>(&g_head[(size_t)q * 256 + m * 32 + j * 4]) = acc;
}

// ---------------- Launch --------------------------------------------------
extern "C" void kernel_launch(void* const* d_in, const int* in_sizes, int n_in,
                              void* d_out, int out_size)
{
    const float* query   = (const float*)d_in[0];
    const float* refpts  = (const float*)d_in[1];
    const float* inflat  = (const float*)d_in[2];
    const float* w_value = (const float*)d_in[5];
    const float* b_value = (const float*)d_in[6];
    const float* w_off   = (const float*)d_in[7];
    const float* b_off   = (const float*)d_in[8];
    const float* w_attn  = (const float*)d_in[9];
    const float* b_attn  = (const float*)d_in[10];
    const float* w_out   = (const float*)d_in[11];
    const float* b_out   = (const float*)d_in[12];
    float* out = (float*)d_out;

    const int M = TOTQ;
    const int mblocks = (M + 127) / 128;   // 348

    prep_weights<<<896, 256>>>(w_value, w_off, w_attn, w_out);

    hmma_gemm<<<dim3(2, mblocks), 256>>>(inflat, b_value, nullptr, M, 256, 0, 0);
    hmma_gemm<<<dim3(2, mblocks), 256>>>(query,  b_off,   nullptr, M, 256, 0, 1);
    hmma_gemm<<<dim3(1, mblocks), 256>>>(query,  b_attn,  nullptr, M, 128, 0, 2);

    const int nwarps  = TOTQ * 2;
    const int nblocks = (nwarps + 7) / 8;
    msda_sample<<<nblocks, 256>>>(refpts);

    hmma_gemm<<<dim3(2, mblocks), 256>>>(nullptr, b_out, out, M, 256, 1, 3);
}

// round 6
// speedup vs baseline: 2.4552x; 1.0590x over previous
#include <cuda_runtime.h>
#include <cuda_bf16.h>
#include <cstdint>

// ---------------- Problem constants (fixed by the dataset) ----------------
#define D_MODEL   256
#define N_HEADS   8
#define HEAD_DIM  32
#define N_LEVELS  4
#define N_POINTS  4
#define LEN_IN    22223
#define NBATCH    2
#define TOTQ      (NBATCH * LEN_IN)   // 44446

__device__ __constant__ int   c_W[4] = {167, 84, 42, 21};
__device__ __constant__ int   c_H[4] = {100, 50, 25, 13};
__device__ __constant__ int   c_ST[4] = {0, 16700, 20900, 21950};

// ---------------- Scratch (device globals; no allocation allowed) ---------
__device__ float g_value[(size_t)TOTQ * 256];
__device__ float g_off  [(size_t)TOTQ * 256];
__device__ float g_attn [(size_t)TOTQ * 128];
__device__ float g_head [(size_t)TOTQ * 256];
// split-bf16 weights, [n][k] row-major (k contiguous, 256 per row)
// [0,65536)=w_value  [65536,131072)=w_off  [131072,163840)=w_attn  [163840,229376)=w_out
__device__ __nv_bfloat16 g_bhi[229376];
__device__ __nv_bfloat16 g_blo[229376];

// ---------------- helpers ---------------------------------------------------
__device__ __forceinline__ uint32_t smem_u32(const void* p) {
    uint32_t a;
    asm("{ .reg .u64 t; cvta.to.shared.u64 t, %1; cvt.u32.u64 %0, t; }" : "=r"(a) : "l"(p));
    return a;
}
__device__ __forceinline__ void split2(float a, float b, uint32_t& hi, uint32_t& lo) {
    const __nv_bfloat16 ha = __float2bfloat16(a);
    const __nv_bfloat16 hb = __float2bfloat16(b);
    hi = ((uint32_t)__bfloat16_as_ushort(hb) << 16) | __bfloat16_as_ushort(ha);
    const __nv_bfloat16 la = __float2bfloat16(a - __bfloat162float(ha));
    const __nv_bfloat16 lb = __float2bfloat16(b - __bfloat162float(hb));
    lo = ((uint32_t)__bfloat16_as_ushort(lb) << 16) | __bfloat16_as_ushort(la);
}
__device__ __forceinline__ void ldm_x4(uint32_t* r, uint32_t addr) {
    asm volatile("ldmatrix.sync.aligned.m8n8.x4.shared.b16 {%0,%1,%2,%3}, [%4];"
                 : "=r"(r[0]), "=r"(r[1]), "=r"(r[2]), "=r"(r[3]) : "r"(addr));
}
__device__ __forceinline__ void mma_bf16(float* d, const uint32_t* a, uint32_t b0, uint32_t b1) {
    asm volatile(
        "mma.sync.aligned.m16n8k16.row.col.f32.bf16.bf16.f32 "
        "{%0,%1,%2,%3}, {%4,%5,%6,%7}, {%8,%9}, {%0,%1,%2,%3};"
        : "+f"(d[0]), "+f"(d[1]), "+f"(d[2]), "+f"(d[3])
        : "r"(a[0]), "r"(a[1]), "r"(a[2]), "r"(a[3]), "r"(b0), "r"(b1));
}

// ---------------- Weight prep: transpose + bf16 hi/lo split ----------------
__global__ void prep_weights(const float* __restrict__ wv, const float* __restrict__ wo,
                             const float* __restrict__ wa, const float* __restrict__ wu)
{
    const int idx = blockIdx.x * 256 + threadIdx.x;
    if (idx >= 229376) return;
    float a;
    if (idx < 65536)       { int l = idx;          int n = l >> 8, k = l & 255; a = wv[k * 256 + n]; }
    else if (idx < 131072) { int l = idx - 65536;  int n = l >> 8, k = l & 255; a = wo[k * 256 + n]; }
    else if (idx < 163840) { int l = idx - 131072; int n = l >> 8, k = l & 255; a = wa[k * 128 + n]; }
    else                   { int l = idx - 163840; int n = l >> 8, k = l & 255; a = wu[k * 256 + n]; }
    const __nv_bfloat16 h = __float2bfloat16(a);
    g_bhi[idx] = h;
    g_blo[idx] = __float2bfloat16(a - __bfloat162float(h));
}

// ---------------- HMMA GEMM body: C = A(fp32) @ W + bias -------------------
// 128x128 CTA tile, BK=32, 8 warps (4m x 2n), warp tile 32x64, m16n8k16.
// 3-pass split bf16: ah*bh + al*bh + ah*bl.
#define SROW 80   // smem row stride (bytes): 32 bf16 + pad (conflict-free)

__device__ __forceinline__ void gemm_body(
    const float* __restrict__ A,
    const __nv_bfloat16* __restrict__ Bhi,
    const __nv_bfloat16* __restrict__ Blo,
    const float* __restrict__ bias,
    float* __restrict__ C,
    int M, int N, int bm, int bn)
{
    __shared__ __align__(16) uint8_t sAh[128 * SROW];
    __shared__ __align__(16) uint8_t sAl[128 * SROW];
    __shared__ __align__(16) uint8_t sBh[128 * SROW];
    __shared__ __align__(16) uint8_t sBl[128 * SROW];

    const int tid  = threadIdx.x;
    const int wid  = tid >> 5;
    const int lane = tid & 31;
    const int warp_m = wid & 3;
    const int warp_n = wid >> 2;

    const uint32_t sAh32 = smem_u32(sAh);
    const uint32_t sAl32 = smem_u32(sAl);

    float acc[2][8][4];
    #pragma unroll
    for (int i = 0; i < 2; i++)
        #pragma unroll
        for (int j = 0; j < 8; j++)
            #pragma unroll
            for (int k = 0; k < 4; k++) acc[i][j][k] = 0.f;

    const int arow = tid >> 1;
    const int akseg = (tid & 1) * 16;
    const int gr = bm + arow;

    #pragma unroll 1
    for (int c = 0; c < 8; c++) {
        const int k0 = c * 32;

        float4 f[4];
        if (gr < M) {
            const float4* s = reinterpret_cast<const float4*>(A + (size_t)gr * 256 + k0 + akseg);
            f[0] = s[0]; f[1] = s[1]; f[2] = s[2]; f[3] = s[3];
        } else {
            f[0] = f[1] = f[2] = f[3] = make_float4(0.f, 0.f, 0.f, 0.f);
        }
        uint4 bhv[2], blv[2];
        int bn_[2], bseg_[2];
        #pragma unroll
        for (int i = 0; i < 2; i++) {
            const int idx = i * 256 + tid;
            const int n   = idx >> 2;
            const int seg = idx & 3;
            bn_[i] = n; bseg_[i] = seg;
            const size_t go = (size_t)(bn + n) * 256 + k0 + seg * 8;
            bhv[i] = *reinterpret_cast<const uint4*>(Bhi + go);
            blv[i] = *reinterpret_cast<const uint4*>(Blo + go);
        }

        __syncthreads();

        {
            uint32_t hp[8], lp[8];
            split2(f[0].x, f[0].y, hp[0], lp[0]);
            split2(f[0].z, f[0].w, hp[1], lp[1]);
            split2(f[1].x, f[1].y, hp[2], lp[2]);
            split2(f[1].z, f[1].w, hp[3], lp[3]);
            split2(f[2].x, f[2].y, hp[4], lp[4]);
            split2(f[2].z, f[2].w, hp[5], lp[5]);
            split2(f[3].x, f[3].y, hp[6], lp[6]);
            split2(f[3].z, f[3].w, hp[7], lp[7]);
            const int off = arow * SROW + akseg * 2;
            *reinterpret_cast<uint4*>(sAh + off)      = make_uint4(hp[0], hp[1], hp[2], hp[3]);
            *reinterpret_cast<uint4*>(sAh + off + 16) = make_uint4(hp[4], hp[5], hp[6], hp[7]);
            *reinterpret_cast<uint4*>(sAl + off)      = make_uint4(lp[0], lp[1], lp[2], lp[3]);
            *reinterpret_cast<uint4*>(sAl + off + 16) = make_uint4(lp[4], lp[5], lp[6], lp[7]);
        }
        #pragma unroll
        for (int i = 0; i < 2; i++) {
            const int off = bn_[i] * SROW + bseg_[i] * 16;
            *reinterpret_cast<uint4*>(sBh + off) = bhv[i];
            *reinterpret_cast<uint4*>(sBl + off) = blv[i];
        }
        __syncthreads();

        #pragma unroll
        for (int ks = 0; ks < 2; ks++) {
            uint32_t ah[2][4], al[2][4];
            #pragma unroll
            for (int ma = 0; ma < 2; ma++) {
                const uint32_t ao = (uint32_t)((warp_m * 32 + ma * 16 + (lane & 15)) * SROW
                                               + ks * 32 + (lane >> 4) * 16);
                ldm_x4(ah[ma], sAh32 + ao);
                ldm_x4(al[ma], sAl32 + ao);
            }
            #pragma unroll
            for (int na = 0; na < 8; na++) {
                const int boff = (warp_n * 64 + na * 8 + (lane >> 2)) * SROW
                                 + ks * 32 + (lane & 3) * 4;
                const uint32_t bh0 = *reinterpret_cast<const uint32_t*>(sBh + boff);
                const uint32_t bh1 = *reinterpret_cast<const uint32_t*>(sBh + boff + 16);
                const uint32_t bl0 = *reinterpret_cast<const uint32_t*>(sBl + boff);
                const uint32_t bl1 = *reinterpret_cast<const uint32_t*>(sBl + boff + 16);
                #pragma unroll
                for (int ma = 0; ma < 2; ma++) {
                    mma_bf16(acc[ma][na], ah[ma], bh0, bh1);
                    mma_bf16(acc[ma][na], al[ma], bh0, bh1);
                    mma_bf16(acc[ma][na], ah[ma], bl0, bl1);
                }
            }
        }
    }

    #pragma unroll
    for (int ma = 0; ma < 2; ma++) {
        const int row0 = bm + warp_m * 32 + ma * 16 + (lane >> 2);
        const int row1 = row0 + 8;
        #pragma unroll
        for (int na = 0; na < 8; na++) {
            const int col = bn + warp_n * 64 + na * 8 + 2 * (lane & 3);
            const float2 bv = *reinterpret_cast<const float2*>(bias + col);
            if (row0 < M) {
                float2 o = make_float2(acc[ma][na][0] + bv.x, acc[ma][na][1] + bv.y);
                *reinterpret_cast<float2*>(&C[(size_t)row0 * N + col]) = o;
            }
            if (row1 < M) {
                float2 o = make_float2(acc[ma][na][2] + bv.x, acc[ma][na][3] + bv.y);
                *reinterpret_cast<float2*>(&C[(size_t)row1 * N + col]) = o;
            }
        }
    }
}

// Fused front GEMMs: grid.x = 5  (0,1: value | 2,3: offsets | 4: attn)
__global__ __launch_bounds__(256, 2)
void front_gemm(const float* __restrict__ query,
                const float* __restrict__ inflat,
                const float* __restrict__ b_value,
                const float* __restrict__ b_off,
                const float* __restrict__ b_attn,
                int M)
{
    const int bx = blockIdx.x;
    const int bm = blockIdx.y * 128;
    if (bx < 2) {
        gemm_body(inflat, g_bhi, g_blo, b_value, g_value, M, 256, bm, bx * 128);
    } else if (bx < 4) {
        gemm_body(query, g_bhi + 65536, g_blo + 65536, b_off, g_off, M, 256, bm, (bx - 2) * 128);
    } else {
        gemm_body(query, g_bhi + 131072, g_blo + 131072, b_attn, g_attn, M, 128, bm, 0);
    }
}

// Final GEMM: out = g_head @ w_out + b_out
__global__ __launch_bounds__(256, 2)
void final_gemm(const float* __restrict__ b_out, float* __restrict__ out, int M)
{
    gemm_body(g_head, g_bhi + 163840, g_blo + 163840, b_out, out,
              M, 256, blockIdx.y * 128, blockIdx.x * 128);
}

// ---------------- Sampling kernel -----------------------------------------
// Warp = 4 heads (8 lanes/head, float4 per lane). 2 warps per query.
// 128-thread blocks for occupancy granularity. Clamped unconditional loads
// with weight zeroing; two accumulator pairs to shorten FFMA chains.
__global__ __launch_bounds__(128)
void msda_sample(const float* __restrict__ ref)
{
    const int warpGlobal = blockIdx.x * 4 + (threadIdx.x >> 5);
    if (warpGlobal >= TOTQ * 2) return;
    const int q        = warpGlobal >> 1;
    const int headBase = (warpGlobal & 1) * 4;
    const int lane     = threadIdx.x & 31;
    const int j        = lane & 7;
    const int m        = headBase + (lane >> 3);
    const int n        = q / LEN_IN;

    // softmax over 16 logits of head m; lane j holds points j and j+8
    const float la = g_attn[(size_t)q * 128 + m * 16 + j];
    const float lb = g_attn[(size_t)q * 128 + m * 16 + 8 + j];
    float mx = fmaxf(la, lb);
    #pragma unroll
    for (int s = 4; s >= 1; s >>= 1)
        mx = fmaxf(mx, __shfl_xor_sync(0xffffffffu, mx, s, 8));
    float ea = __expf(la - mx);
    float eb = __expf(lb - mx);
    float sum = ea + eb;
    #pragma unroll
    for (int s = 4; s >= 1; s >>= 1)
        sum += __shfl_xor_sync(0xffffffffu, sum, s, 8);
    const float inv = 1.f / sum;
    const float wa = ea * inv;
    const float wb = eb * inv;

    const float4 off = *reinterpret_cast<const float4*>(
        &g_off[(size_t)q * 256 + m * 32 + j * 4]);

    float4 accA = make_float4(0.f, 0.f, 0.f, 0.f);
    float4 accB = make_float4(0.f, 0.f, 0.f, 0.f);
    const float* vbase = g_value + (size_t)n * LEN_IN * 256 + m * 32 + j * 4;

    #pragma unroll
    for (int l = 0; l < N_LEVELS; l++) {
        const int   Wi = c_W[l], Hi = c_H[l];
        const float Wf = (float)Wi, Hf = (float)Hi;
        const float2 r = *reinterpret_cast<const float2*>(&ref[((size_t)q * 4 + l) * 2]);
        const float* vlev = vbase + (size_t)c_ST[l] * 256;

        #pragma unroll
        for (int p = 0; p < N_POINTS; p++) {
            const int pt = l * 4 + p;
            const float w_lp = __shfl_sync(0xffffffffu, (pt < 8) ? wa : wb, pt & 7, 8);
            const float ox = __shfl_sync(0xffffffffu, (pt & 1) ? off.z : off.x, pt >> 1, 8);
            const float oy = __shfl_sync(0xffffffffu, (pt & 1) ? off.w : off.y, pt >> 1, 8);

            const float x = fmaf(r.x, Wf, ox) - 0.5f;
            const float y = fmaf(r.y, Hf, oy) - 0.5f;
            const float x0f = floorf(x);
            const float y0f = floorf(y);
            const float lx = x - x0f;
            const float ly = y - y0f;
            const int x0 = (int)x0f;
            const int y0 = (int)y0f;

            // validity -> multiplicative masks; indices clamped for safe loads
            const float fx0 = ((unsigned)x0 < (unsigned)Wi) ? 1.f : 0.f;
            const float fx1 = ((unsigned)(x0 + 1) < (unsigned)Wi) ? 1.f : 0.f;
            const float fy0 = ((unsigned)y0 < (unsigned)Hi) ? 1.f : 0.f;
            const float fy1 = ((unsigned)(y0 + 1) < (unsigned)Hi) ? 1.f : 0.f;
            const int cx0 = min(max(x0, 0), Wi - 1);
            const int cx1 = min(max(x0 + 1, 0), Wi - 1);
            const int cy0 = min(max(y0, 0), Hi - 1);
            const int cy1 = min(max(y0 + 1, 0), Hi - 1);

            const float w00 = (1.f - lx) * (1.f - ly) * w_lp * (fx0 * fy0);
            const float w01 = lx * (1.f - ly) * w_lp * (fx1 * fy0);
            const float w10 = (1.f - lx) * ly * w_lp * (fx0 * fy1);
            const float w11 = lx * ly * w_lp * (fx1 * fy1);

            const float* r0 = vlev + (size_t)(cy0 * Wi) * 256;
            const float* r1 = vlev + (size_t)(cy1 * Wi) * 256;
            const float4 v00 = *reinterpret_cast<const float4*>(&r0[(size_t)cx0 * 256]);
            const float4 v01 = *reinterpret_cast<const float4*>(&r0[(size_t)cx1 * 256]);
            const float4 v10 = *reinterpret_cast<const float4*>(&r1[(size_t)cx0 * 256]);
            const float4 v11 = *reinterpret_cast<const float4*>(&r1[(size_t)cx1 * 256]);

            accA.x = fmaf(v00.x, w00, accA.x); accA.y = fmaf(v00.y, w00, accA.y);
            accA.z = fmaf(v00.z, w00, accA.z); accA.w = fmaf(v00.w, w00, accA.w);
            accB.x = fmaf(v01.x, w01, accB.x); accB.y = fmaf(v01.y, w01, accB.y);
            accB.z = fmaf(v01.z, w01, accB.z); accB.w = fmaf(v01.w, w01, accB.w);
            accB.x = fmaf(v10.x, w10, accB.x); accB.y = fmaf(v10.y, w10, accB.y);
            accB.z = fmaf(v10.z, w10, accB.z); accB.w = fmaf(v10.w, w10, accB.w);
            accA.x = fmaf(v11.x, w11, accA.x); accA.y = fmaf(v11.y, w11, accA.y);
            accA.z = fmaf(v11.z, w11, accA.z); accA.w = fmaf(v11.w, w11, accA.w);
        }
    }

    float4 o;
    o.x = accA.x + accB.x; o.y = accA.y + accB.y;
    o.z = accA.z + accB.z; o.w = accA.w + accB.w;
    *reinterpret_cast<float4*>(&g_head[(size_t)q * 256 + m * 32 + j * 4]) = o;
}

// ---------------- Launch --------------------------------------------------
extern "C" void kernel_launch(void* const* d_in, const int* in_sizes, int n_in,
                              void* d_out, int out_size)
{
    const float* query   = (const float*)d_in[0];
    const float* refpts  = (const float*)d_in[1];
    const float* inflat  = (const float*)d_in[2];
    const float* w_value = (const float*)d_in[5];
    const float* b_value = (const float*)d_in[6];
    const float* w_off   = (const float*)d_in[7];
    const float* b_off   = (const float*)d_in[8];
    const float* w_attn  = (const float*)d_in[9];
    const float* b_attn  = (const float*)d_in[10];
    const float* w_out   = (const float*)d_in[11];
    const float* b_out   = (const float*)d_in[12];
    float* out = (float*)d_out;

    const int M = TOTQ;
    const int mblocks = (M + 127) / 128;   // 348

    prep_weights<<<896, 256>>>(w_value, w_off, w_attn, w_out);

    front_gemm<<<dim3(5, mblocks), 256>>>(query, inflat, b_value, b_off, b_attn, M);

    const int nwarps  = TOTQ * 2;
    const int nblocks = (nwarps + 3) / 4;
    msda_sample<<<nblocks, 128>>>(refpts);

    final_gemm<<<dim3(2, mblocks), 256>>>(b_out, out, M);
}

// round 7
// speedup vs baseline: 2.8894x; 1.1768x over previous
#include <cuda_runtime.h>
#include <cuda_bf16.h>
#include <cuda_fp16.h>
#include <cstdint>

// ---------------- Problem constants (fixed by the dataset) ----------------
#define D_MODEL   256
#define N_HEADS   8
#define HEAD_DIM  32
#define N_LEVELS  4
#define N_POINTS  4
#define LEN_IN    22223
#define NBATCH    2
#define TOTQ      (NBATCH * LEN_IN)   // 44446

__device__ __constant__ int   c_W[4] = {167, 84, 42, 21};
__device__ __constant__ int   c_H[4] = {100, 50, 25, 13};
__device__ __constant__ int   c_ST[4] = {0, 16700, 20900, 21950};

// ---------------- Scratch (device globals; no allocation allowed) ---------
__device__ __half g_value[(size_t)TOTQ * 256];   // fp16 value (written by GEMM)
__device__ float  g_off  [(size_t)TOTQ * 256];
__device__ float  g_attn [(size_t)TOTQ * 128];
__device__ float  g_head [(size_t)TOTQ * 256];
// split-bf16 weights, [n][k] row-major (k contiguous, 256 per row)
// [0,65536)=w_value  [65536,131072)=w_off  [131072,163840)=w_attn  [163840,229376)=w_out
__device__ __nv_bfloat16 g_bhi[229376];
__device__ __nv_bfloat16 g_blo[229376];

// ---------------- helpers ---------------------------------------------------
__device__ __forceinline__ uint32_t smem_u32(const void* p) {
    uint32_t a;
    asm("{ .reg .u64 t; cvta.to.shared.u64 t, %1; cvt.u32.u64 %0, t; }" : "=r"(a) : "l"(p));
    return a;
}
__device__ __forceinline__ void split2(float a, float b, uint32_t& hi, uint32_t& lo) {
    const __nv_bfloat16 ha = __float2bfloat16(a);
    const __nv_bfloat16 hb = __float2bfloat16(b);
    hi = ((uint32_t)__bfloat16_as_ushort(hb) << 16) | __bfloat16_as_ushort(ha);
    const __nv_bfloat16 la = __float2bfloat16(a - __bfloat162float(ha));
    const __nv_bfloat16 lb = __float2bfloat16(b - __bfloat162float(hb));
    lo = ((uint32_t)__bfloat16_as_ushort(lb) << 16) | __bfloat16_as_ushort(la);
}
__device__ __forceinline__ void ldm_x4(uint32_t* r, uint32_t addr) {
    asm volatile("ldmatrix.sync.aligned.m8n8.x4.shared.b16 {%0,%1,%2,%3}, [%4];"
                 : "=r"(r[0]), "=r"(r[1]), "=r"(r[2]), "=r"(r[3]) : "r"(addr));
}
__device__ __forceinline__ void mma_bf16(float* d, const uint32_t* a, uint32_t b0, uint32_t b1) {
    asm volatile(
        "mma.sync.aligned.m16n8k16.row.col.f32.bf16.bf16.f32 "
        "{%0,%1,%2,%3}, {%4,%5,%6,%7}, {%8,%9}, {%0,%1,%2,%3};"
        : "+f"(d[0]), "+f"(d[1]), "+f"(d[2]), "+f"(d[3])
        : "r"(a[0]), "r"(a[1]), "r"(a[2]), "r"(a[3]), "r"(b0), "r"(b1));
}

// ---------------- Weight prep: transpose + bf16 hi/lo split ----------------
__global__ void prep_weights(const float* __restrict__ wv, const float* __restrict__ wo,
                             const float* __restrict__ wa, const float* __restrict__ wu)
{
    const int idx = blockIdx.x * 256 + threadIdx.x;
    if (idx >= 229376) return;
    float a;
    if (idx < 65536)       { int l = idx;          int n = l >> 8, k = l & 255; a = wv[k * 256 + n]; }
    else if (idx < 131072) { int l = idx - 65536;  int n = l >> 8, k = l & 255; a = wo[k * 256 + n]; }
    else if (idx < 163840) { int l = idx - 131072; int n = l >> 8, k = l & 255; a = wa[k * 128 + n]; }
    else                   { int l = idx - 163840; int n = l >> 8, k = l & 255; a = wu[k * 256 + n]; }
    const __nv_bfloat16 h = __float2bfloat16(a);
    g_bhi[idx] = h;
    g_blo[idx] = __float2bfloat16(a - __bfloat162float(h));
}

// ---------------- HMMA GEMM body: C = A(fp32) @ W + bias -------------------
// 128x128 CTA tile, BK=32, 8 warps (4m x 2n), warp tile 32x64, m16n8k16.
// 3-pass split bf16, double-buffered smem (1 barrier per K-chunk).
#define SROW 80               // smem row stride (bytes): 32 bf16 + pad
#define REGN (128 * SROW)     // 10240 bytes per region
#define BUFB (4 * REGN)       // 40960 bytes per buffer (Ah, Al, Bh, Bl)

template<typename OutT>
__device__ __forceinline__ void gemm_body(
    const float* __restrict__ A,
    const __nv_bfloat16* __restrict__ Bhi,
    const __nv_bfloat16* __restrict__ Blo,
    const float* __restrict__ bias,
    OutT* __restrict__ C,
    int M, int N, int bm, int bn)
{
    extern __shared__ uint8_t dyns[];
    const uint32_t sbase = smem_u32(dyns);

    const int tid  = threadIdx.x;
    const int wid  = tid >> 5;
    const int lane = tid & 31;
    const int warp_m = wid & 3;
    const int warp_n = wid >> 2;

    float acc[2][8][4];
    #pragma unroll
    for (int i = 0; i < 2; i++)
        #pragma unroll
        for (int j = 0; j < 8; j++)
            #pragma unroll
            for (int k = 0; k < 4; k++) acc[i][j][k] = 0.f;

    const int arow  = tid >> 1;
    const int akseg = (tid & 1) * 16;
    const int gr    = bm + arow;
    // B store mapping (constant across chunks)
    const int bn0   = tid >> 2;             // idx = tid
    const int bs0   = tid & 3;
    const int bn1   = (256 + tid) >> 2;     // idx = 256 + tid
    const int bs1   = (256 + tid) & 3;

    float4 f[4];
    uint4 bhv[2], blv[2];

    auto load_regs = [&](int c) {
        const int k0 = c * 32;
        if (gr < M) {
            const float4* s = reinterpret_cast<const float4*>(A + (size_t)gr * 256 + k0 + akseg);
            f[0] = s[0]; f[1] = s[1]; f[2] = s[2]; f[3] = s[3];
        } else {
            f[0] = f[1] = f[2] = f[3] = make_float4(0.f, 0.f, 0.f, 0.f);
        }
        const size_t g0 = (size_t)(bn + bn0) * 256 + k0 + bs0 * 8;
        const size_t g1 = (size_t)(bn + bn1) * 256 + k0 + bs1 * 8;
        bhv[0] = *reinterpret_cast<const uint4*>(Bhi + g0);
        blv[0] = *reinterpret_cast<const uint4*>(Blo + g0);
        bhv[1] = *reinterpret_cast<const uint4*>(Bhi + g1);
        blv[1] = *reinterpret_cast<const uint4*>(Blo + g1);
    };

    auto store_chunk = [&](int b) {
        uint8_t* sAh = dyns + b * BUFB;
        uint8_t* sAl = sAh + REGN;
        uint8_t* sBh = sAl + REGN;
        uint8_t* sBl = sBh + REGN;
        uint32_t hp[8], lp[8];
        split2(f[0].x, f[0].y, hp[0], lp[0]);
        split2(f[0].z, f[0].w, hp[1], lp[1]);
        split2(f[1].x, f[1].y, hp[2], lp[2]);
        split2(f[1].z, f[1].w, hp[3], lp[3]);
        split2(f[2].x, f[2].y, hp[4], lp[4]);
        split2(f[2].z, f[2].w, hp[5], lp[5]);
        split2(f[3].x, f[3].y, hp[6], lp[6]);
        split2(f[3].z, f[3].w, hp[7], lp[7]);
        const int aoff = arow * SROW + akseg * 2;
        *reinterpret_cast<uint4*>(sAh + aoff)      = make_uint4(hp[0], hp[1], hp[2], hp[3]);
        *reinterpret_cast<uint4*>(sAh + aoff + 16) = make_uint4(hp[4], hp[5], hp[6], hp[7]);
        *reinterpret_cast<uint4*>(sAl + aoff)      = make_uint4(lp[0], lp[1], lp[2], lp[3]);
        *reinterpret_cast<uint4*>(sAl + aoff + 16) = make_uint4(lp[4], lp[5], lp[6], lp[7]);
        const int b0off = bn0 * SROW + bs0 * 16;
        const int b1off = bn1 * SROW + bs1 * 16;
        *reinterpret_cast<uint4*>(sBh + b0off) = bhv[0];
        *reinterpret_cast<uint4*>(sBl + b0off) = blv[0];
        *reinterpret_cast<uint4*>(sBh + b1off) = bhv[1];
        *reinterpret_cast<uint4*>(sBl + b1off) = blv[1];
    };

    auto compute_chunk = [&](int b) {
        const uint32_t aAh = sbase + b * BUFB;
        const uint32_t aAl = aAh + REGN;
        const uint8_t* sBh = dyns + b * BUFB + 2 * REGN;
        const uint8_t* sBl = dyns + b * BUFB + 3 * REGN;
        #pragma unroll
        for (int ks = 0; ks < 2; ks++) {
            uint32_t ah[2][4], al[2][4];
            #pragma unroll
            for (int ma = 0; ma < 2; ma++) {
                const uint32_t ao = (uint32_t)((warp_m * 32 + ma * 16 + (lane & 15)) * SROW
                                               + ks * 32 + (lane >> 4) * 16);
                ldm_x4(ah[ma], aAh + ao);
                ldm_x4(al[ma], aAl + ao);
            }
            #pragma unroll
            for (int na = 0; na < 8; na++) {
                const int boff = (warp_n * 64 + na * 8 + (lane >> 2)) * SROW
                                 + ks * 32 + (lane & 3) * 4;
                const uint32_t bh0 = *reinterpret_cast<const uint32_t*>(sBh + boff);
                const uint32_t bh1 = *reinterpret_cast<const uint32_t*>(sBh + boff + 16);
                const uint32_t bl0 = *reinterpret_cast<const uint32_t*>(sBl + boff);
                const uint32_t bl1 = *reinterpret_cast<const uint32_t*>(sBl + boff + 16);
                #pragma unroll
                for (int ma = 0; ma < 2; ma++) {
                    mma_bf16(acc[ma][na], ah[ma], bh0, bh1);
                    mma_bf16(acc[ma][na], al[ma], bh0, bh1);
                    mma_bf16(acc[ma][na], ah[ma], bl0, bl1);
                }
            }
        }
    };

    // prologue
    load_regs(0);
    store_chunk(0);
    __syncthreads();

    #pragma unroll 1
    for (int c = 0; c < 8; c++) {
        if (c < 7) load_regs(c + 1);
        compute_chunk(c & 1);
        if (c < 7) {
            store_chunk((c + 1) & 1);
            __syncthreads();
        }
    }

    // epilogue: bias + store
    #pragma unroll
    for (int ma = 0; ma < 2; ma++) {
        const int row0 = bm + warp_m * 32 + ma * 16 + (lane >> 2);
        const int row1 = row0 + 8;
        #pragma unroll
        for (int na = 0; na < 8; na++) {
            const int col = bn + warp_n * 64 + na * 8 + 2 * (lane & 3);
            const float2 bv = *reinterpret_cast<const float2*>(bias + col);
            if constexpr (sizeof(OutT) == 2) {
                if (row0 < M) {
                    __half2 o = __floats2half2_rn(acc[ma][na][0] + bv.x, acc[ma][na][1] + bv.y);
                    *reinterpret_cast<__half2*>(&C[(size_t)row0 * N + col]) = o;
                }
                if (row1 < M) {
                    __half2 o = __floats2half2_rn(acc[ma][na][2] + bv.x, acc[ma][na][3] + bv.y);
                    *reinterpret_cast<__half2*>(&C[(size_t)row1 * N + col]) = o;
                }
            } else {
                if (row0 < M) {
                    float2 o = make_float2(acc[ma][na][0] + bv.x, acc[ma][na][1] + bv.y);
                    *reinterpret_cast<float2*>(&C[(size_t)row0 * N + col]) = o;
                }
                if (row1 < M) {
                    float2 o = make_float2(acc[ma][na][2] + bv.x, acc[ma][na][3] + bv.y);
                    *reinterpret_cast<float2*>(&C[(size_t)row1 * N + col]) = o;
                }
            }
        }
    }
}

// Fused front GEMMs: grid.x = 5  (0,1: value->fp16 | 2,3: offsets | 4: attn)
__global__ __launch_bounds__(256, 2)
void front_gemm(const float* __restrict__ query,
                const float* __restrict__ inflat,
                const float* __restrict__ b_value,
                const float* __restrict__ b_off,
                const float* __restrict__ b_attn,
                int M)
{
    const int bx = blockIdx.x;
    const int bm = blockIdx.y * 128;
    if (bx < 2) {
        gemm_body<__half>(inflat, g_bhi, g_blo, b_value, g_value, M, 256, bm, bx * 128);
    } else if (bx < 4) {
        gemm_body<float>(query, g_bhi + 65536, g_blo + 65536, b_off, g_off, M, 256, bm, (bx - 2) * 128);
    } else {
        gemm_body<float>(query, g_bhi + 131072, g_blo + 131072, b_attn, g_attn, M, 128, bm, 0);
    }
}

// Final GEMM: out = g_head @ w_out + b_out
__global__ __launch_bounds__(256, 2)
void final_gemm(const float* __restrict__ b_out, float* __restrict__ out, int M)
{
    gemm_body<float>(g_head, g_bhi + 163840, g_blo + 163840, b_out, out,
                     M, 256, blockIdx.y * 128, blockIdx.x * 128);
}

// ---------------- Sampling kernel -----------------------------------------
// One warp per query. lane = head*4 + quad; each lane handles 8 fp16 channels.
// Softmax/offsets distributed over 4-lane segments (width-4 shuffles).
__device__ __forceinline__ void acc8(float* a, const uint4& v, float w) {
    const __half2* h = reinterpret_cast<const __half2*>(&v);
    #pragma unroll
    for (int i = 0; i < 4; i++) {
        const float2 f = __half22float2(h[i]);
        a[2 * i]     = fmaf(f.x, w, a[2 * i]);
        a[2 * i + 1] = fmaf(f.y, w, a[2 * i + 1]);
    }
}

__global__ __launch_bounds__(128)
void msda_sample(const float* __restrict__ ref)
{
    const int q = blockIdx.x * 4 + (threadIdx.x >> 5);
    if (q >= TOTQ) return;
    const int lane = threadIdx.x & 31;
    const int m = lane >> 2;        // head 0..7
    const int j = lane & 3;         // quad 0..3 (8 channels)
    const int n = (q >= LEN_IN) ? 1 : 0;

    // softmax: lane j holds logits j*4..j*4+3 of head m
    const float4 lg = *reinterpret_cast<const float4*>(&g_attn[(size_t)q * 128 + m * 16 + j * 4]);
    float mx = fmaxf(fmaxf(lg.x, lg.y), fmaxf(lg.z, lg.w));
    mx = fmaxf(mx, __shfl_xor_sync(0xffffffffu, mx, 1, 4));
    mx = fmaxf(mx, __shfl_xor_sync(0xffffffffu, mx, 2, 4));
    const float e0 = __expf(lg.x - mx), e1 = __expf(lg.y - mx);
    const float e2 = __expf(lg.z - mx), e3 = __expf(lg.w - mx);
    float sum = e0 + e1 + e2 + e3;
    sum += __shfl_xor_sync(0xffffffffu, sum, 1, 4);
    sum += __shfl_xor_sync(0xffffffffu, sum, 2, 4);
    const float inv = 1.f / sum;
    const float w0 = e0 * inv, w1 = e1 * inv, w2 = e2 * inv, w3 = e3 * inv;

    // offsets: lane j holds 8 floats = points 4j..4j+3? no: floats j*8..j*8+7 = points j*4..j*4+3
    const float4 o0 = *reinterpret_cast<const float4*>(&g_off[(size_t)q * 256 + m * 32 + j * 8]);
    const float4 o1 = *reinterpret_cast<const float4*>(&g_off[(size_t)q * 256 + m * 32 + j * 8 + 4]);

    float acc[8];
    #pragma unroll
    for (int i = 0; i < 8; i++) acc[i] = 0.f;

    const __half* vbase = g_value + ((size_t)n * LEN_IN) * 256 + m * 32 + j * 8;

    #pragma unroll
    for (int l = 0; l < N_LEVELS; l++) {
        const int   Wi = c_W[l], Hi = c_H[l];
        const float Wf = (float)Wi, Hf = (float)Hi;
        const float2 r = *reinterpret_cast<const float2*>(&ref[((size_t)q * 4 + l) * 2]);
        const __half* vlev = vbase + (size_t)c_ST[l] * 256;

        #pragma unroll
        for (int p = 0; p < N_POINTS; p++) {
            const int pt = l * 4 + p;          // 0..15; holder lane = pt>>2, slot = pt&3
            const int sl = pt & 3;
            const float wsel = (sl == 0) ? w0 : (sl == 1) ? w1 : (sl == 2) ? w2 : w3;
            const float oxsel = (sl == 0) ? o0.x : (sl == 1) ? o0.z : (sl == 2) ? o1.x : o1.z;
            const float oysel = (sl == 0) ? o0.y : (sl == 1) ? o0.w : (sl == 2) ? o1.y : o1.w;
            const float w_lp = __shfl_sync(0xffffffffu, wsel, pt >> 2, 4);
            const float ox   = __shfl_sync(0xffffffffu, oxsel, pt >> 2, 4);
            const float oy   = __shfl_sync(0xffffffffu, oysel, pt >> 2, 4);

            const float x = fmaf(r.x, Wf, ox) - 0.5f;
            const float y = fmaf(r.y, Hf, oy) - 0.5f;
            const float x0f = floorf(x);
            const float y0f = floorf(y);
            const float lx = x - x0f;
            const float ly = y - y0f;
            const int x0 = (int)x0f;
            const int y0 = (int)y0f;

            const float fx0 = ((unsigned)x0 < (unsigned)Wi) ? 1.f : 0.f;
            const float fx1 = ((unsigned)(x0 + 1) < (unsigned)Wi) ? 1.f : 0.f;
            const float fy0 = ((unsigned)y0 < (unsigned)Hi) ? 1.f : 0.f;
            const float fy1 = ((unsigned)(y0 + 1) < (unsigned)Hi) ? 1.f : 0.f;
            const int cx0 = min(max(x0, 0), Wi - 1);
            const int cx1 = min(max(x0 + 1, 0), Wi - 1);
            const int cy0 = min(max(y0, 0), Hi - 1);
            const int cy1 = min(max(y0 + 1, 0), Hi - 1);

            const float w00 = (1.f - lx) * (1.f - ly) * w_lp * (fx0 * fy0);
            const float w01 = lx * (1.f - ly) * w_lp * (fx1 * fy0);
            const float w10 = (1.f - lx) * ly * w_lp * (fx0 * fy1);
            const float w11 = lx * ly * w_lp * (fx1 * fy1);

            const __half* r0 = vlev + (size_t)(cy0 * Wi) * 256;
            const __half* r1 = vlev + (size_t)(cy1 * Wi) * 256;
            const uint4 v00 = *reinterpret_cast<const uint4*>(r0 + (size_t)cx0 * 256);
            const uint4 v01 = *reinterpret_cast<const uint4*>(r0 + (size_t)cx1 * 256);
            const uint4 v10 = *reinterpret_cast<const uint4*>(r1 + (size_t)cx0 * 256);
            const uint4 v11 = *reinterpret_cast<const uint4*>(r1 + (size_t)cx1 * 256);

            acc8(acc, v00, w00);
            acc8(acc, v01, w01);
            acc8(acc, v10, w10);
            acc8(acc, v11, w11);
        }
    }

    float* dst = &g_head[(size_t)q * 256 + m * 32 + j * 8];
    *reinterpret_cast<float4*>(dst)     = make_float4(acc[0], acc[1], acc[2], acc[3]);
    *reinterpret_cast<float4*>(dst + 4) = make_float4(acc[4], acc[5], acc[6], acc[7]);
}

// ---------------- Launch --------------------------------------------------
extern "C" void kernel_launch(void* const* d_in, const int* in_sizes, int n_in,
                              void* d_out, int out_size)
{
    const float* query   = (const float*)d_in[0];
    const float* refpts  = (const float*)d_in[1];
    const float* inflat  = (const float*)d_in[2];
    const float* w_value = (const float*)d_in[5];
    const float* b_value = (const float*)d_in[6];
    const float* w_off   = (const float*)d_in[7];
    const float* b_off   = (const float*)d_in[8];
    const float* w_attn  = (const float*)d_in[9];
    const float* b_attn  = (const float*)d_in[10];
    const float* w_out   = (const float*)d_in[11];
    const float* b_out   = (const float*)d_in[12];
    float* out = (float*)d_out;

    const int SMEM = 2 * BUFB;   // 81920
    cudaFuncSetAttribute(front_gemm, cudaFuncAttributeMaxDynamicSharedMemorySize, SMEM);
    cudaFuncSetAttribute(final_gemm, cudaFuncAttributeMaxDynamicSharedMemorySize, SMEM);

    const int M = TOTQ;
    const int mblocks = (M + 127) / 128;   // 348

    prep_weights<<<896, 256>>>(w_value, w_off, w_attn, w_out);

    front_gemm<<<dim3(5, mblocks), 256, SMEM>>>(query, inflat, b_value, b_off, b_attn, M);

    const int nblocks = (TOTQ + 3) / 4;
    msda_sample<<<nblocks, 128>>>(refpts);

    final_gemm<<<dim3(2, mblocks), 256, SMEM>>>(b_out, out, M);
}